// round 16
// baseline (speedup 1.0000x reference)
#include <cuda_runtime.h>
#include <cuda_fp16.h>
#include <cstdint>

#define NN     100000
#define HH     128
#define TT     32
#define MDIM   16
#define ES     600000
#define ED     600000

// ---------------- scratch ----------------
__device__ __align__(16) __half g_Ps[NN * TT];   // fp16 x@W[:H]
__device__ __align__(16) __half g_Pd[NN * TT];   // fp16 x@W[H:] + b_trans
__device__ float g_ew_s[ES];
__device__ float g_ew_d[ED];
// propagation state: fp32 accumulator (atomics) + fp16 read mirror
__device__ __align__(16) float  g_n32pos[NN * MDIM];
__device__ __align__(16) float  g_n32dom[NN * MDIM];
__device__ __align__(16) __half g_c16pos[NN * MDIM];
__device__ __align__(16) __half g_c16dom[NN * MDIM];

// ---------------- helpers ----------------
__device__ __forceinline__ float fast_tanh(float s) {
    float r; asm("tanh.approx.f32 %0, %1;" : "=f"(r) : "f"(s)); return r;
}
__device__ __forceinline__ unsigned su32(const void* p) {
    return (unsigned)__cvta_generic_to_shared(p);
}

// ---------------- kernel 1: HMMA node projections + fused init -------------
#define XS_STRIDE 136
#define WP_STRIDE 72

__global__ void __launch_bounds__(128) proj_kernel(const float* __restrict__ x,
                                                   const float* __restrict__ Wt,
                                                   const float* __restrict__ bt,
                                                   const float* __restrict__ mask) {
    __shared__ __align__(16) __half Wp[128 * WP_STRIDE];
    __shared__ __align__(16) __half xs[64 * XS_STRIDE];
    int tid = threadIdx.x;
    int n0 = blockIdx.x * 64;

    // ---- fused init: mask -> n32 (fp32) + c16 (fp16), grid-stride ----
    {
        const int n4 = NN * MDIM / 4;
        for (int i = blockIdx.x * 128 + tid; i < n4; i += gridDim.x * 128) {
            float4 v = reinterpret_cast<const float4*>(mask)[i];
            reinterpret_cast<float4*>(g_n32pos)[i] = v;
            reinterpret_cast<float4*>(g_n32dom)[i] = v;
            __half2 h0 = __floats2half2_rn(v.x, v.y);
            __half2 h1 = __floats2half2_rn(v.z, v.w);
            uint2 packed = make_uint2(*reinterpret_cast<unsigned*>(&h0),
                                      *reinterpret_cast<unsigned*>(&h1));
            reinterpret_cast<uint2*>(g_c16pos)[i] = packed;
            reinterpret_cast<uint2*>(g_c16dom)[i] = packed;
        }
    }

    for (int i = tid; i < 128 * 64; i += 128) {
        int h = i >> 6, j = i & 63;
        float w = (j < 32) ? Wt[h * 32 + j] : Wt[(128 + h) * 32 + (j - 32)];
        Wp[h * WP_STRIDE + j] = __float2half_rn(w);
    }
    for (int i = tid; i < 64 * 32; i += 128) {
        int r = i >> 5, c4 = i & 31;
        int node = n0 + r;
        float4 v = (node < NN)
                 ? reinterpret_cast<const float4*>(x)[(size_t)node * 32 + c4]
                 : make_float4(0.f, 0.f, 0.f, 0.f);
        *reinterpret_cast<__half2*>(&xs[r * XS_STRIDE + c4 * 4])     = __floats2half2_rn(v.x, v.y);
        *reinterpret_cast<__half2*>(&xs[r * XS_STRIDE + c4 * 4 + 2]) = __floats2half2_rn(v.z, v.w);
    }
    __syncthreads();

    int warp = tid >> 5, lane = tid & 31;
    int wb = warp * 16;

    float acc[8][4];
#pragma unroll
    for (int nt = 0; nt < 8; nt++)
#pragma unroll
        for (int j = 0; j < 4; j++) acc[nt][j] = 0.f;

    int a_row = wb + (lane & 15);
    int a_coff = (lane >> 4) * 8;
    int b_row = (lane & 15);

#pragma unroll
    for (int k = 0; k < 8; k++) {
        unsigned a0, a1, a2, a3;
        unsigned addrA = su32(&xs[a_row * XS_STRIDE + k * 16 + a_coff]);
        asm volatile("ldmatrix.sync.aligned.m8n8.x4.shared.b16 {%0,%1,%2,%3}, [%4];"
                     : "=r"(a0), "=r"(a1), "=r"(a2), "=r"(a3) : "r"(addrA));
#pragma unroll
        for (int nt = 0; nt < 8; nt++) {
            unsigned b0, b1;
            unsigned addrB = su32(&Wp[(k * 16 + b_row) * WP_STRIDE + nt * 8]);
            asm volatile("ldmatrix.sync.aligned.m8n8.x2.trans.shared.b16 {%0,%1}, [%2];"
                         : "=r"(b0), "=r"(b1) : "r"(addrB));
            asm volatile("mma.sync.aligned.m16n8k16.row.col.f32.f16.f16.f32 "
                         "{%0,%1,%2,%3}, {%4,%5,%6,%7}, {%8,%9}, {%0,%1,%2,%3};"
                         : "+f"(acc[nt][0]), "+f"(acc[nt][1]), "+f"(acc[nt][2]), "+f"(acc[nt][3])
                         : "r"(a0), "r"(a1), "r"(a2), "r"(a3), "r"(b0), "r"(b1));
        }
    }

    int row_l = wb + (lane >> 2);
    int col0 = (lane & 3) * 2;
#pragma unroll
    for (int nt = 0; nt < 8; nt++) {
        bool isPs = (nt < 4);
        __half* base = isPs ? g_Ps : g_Pd;
        int cc = isPs ? (nt * 8 + col0) : (nt * 8 + col0 - 32);
        float b0 = isPs ? 0.f : bt[cc];
        float b1 = isPs ? 0.f : bt[cc + 1];
        int nodeA = n0 + row_l;
        int nodeB = nodeA + 8;
        if (nodeA < NN)
            *reinterpret_cast<__half2*>(&base[(size_t)nodeA * TT + cc]) =
                __floats2half2_rn(acc[nt][0] + b0, acc[nt][1] + b1);
        if (nodeB < NN)
            *reinterpret_cast<__half2*>(&base[(size_t)nodeB * TT + cc]) =
                __floats2half2_rn(acc[nt][2] + b0, acc[nt][3] + b1);
    }
}

// ---------------- kernel 2: FUSED gate + propagation round 1 ---------------
// 2 lanes/edge. ALL six random loads (Ps x2, Pd x2, c16[src], n32[dst] x2)
// are hoisted to the top -> single latency exposure, compute in load shadow.
__global__ void ewprop_kernel(const int* __restrict__ si, const int* __restrict__ di,
                              const float* __restrict__ sattr, const float* __restrict__ dattr,
                              const float* __restrict__ Wpos, const float* __restrict__ bpos,
                              const float* __restrict__ Wdom, const float* __restrict__ bdom) {
    long long gid = (long long)blockIdx.x * blockDim.x + threadIdx.x;
    long long eg = gid >> 1;
    int sub = (int)(gid & 1);      // half: channels [sub*16, sub*16+16)
    if (eg >= (long long)(ES + ED)) return;

    bool spatial = (eg < ES);
    int e = spatial ? (int)eg : (int)(eg - ES);
    const int* eidx = spatial ? si : di;
    int nE = spatial ? ES : ED;
    int src = eidx[e];
    int dst = eidx[nE + e];

    // ---- front-batched random loads (MLP ~7) ----
    const __half* psrow = &g_Ps[(size_t)src * TT + sub * 16];
    const __half* pdrow = &g_Pd[(size_t)dst * TT + sub * 16];
    const __half* csrow = spatial ? &g_c16pos[(size_t)src * MDIM + sub * 8]
                                  : &g_c16dom[(size_t)src * MDIM + sub * 8];
    float* nrow = spatial ? &g_n32pos[(size_t)dst * MDIM + sub * 8]
                          : &g_n32dom[(size_t)dst * MDIM + sub * 8];
    uint4 pa0 = *reinterpret_cast<const uint4*>(psrow);
    uint4 pa1 = *reinterpret_cast<const uint4*>(psrow + 8);
    uint4 pb0 = *reinterpret_cast<const uint4*>(pdrow);
    uint4 pb1 = *reinterpret_cast<const uint4*>(pdrow + 8);
    uint4 sr  = *reinterpret_cast<const uint4*>(csrow);
    const float4* drow = reinterpret_cast<const float4*>(nrow);
    float4 dA = drow[0], dB = drow[1];

    const __half2* ph0 = reinterpret_cast<const __half2*>(&pa0);
    const __half2* ph1 = reinterpret_cast<const __half2*>(&pa1);
    const __half2* qh0 = reinterpret_cast<const __half2*>(&pb0);
    const __half2* qh1 = reinterpret_cast<const __half2*>(&pb1);

    float th[16];
#pragma unroll
    for (int j = 0; j < 4; j++) {
        float2 a = __half22float2(ph0[j]);
        float2 b = __half22float2(qh0[j]);
        th[2 * j]     = fast_tanh(a.x + b.x);
        th[2 * j + 1] = fast_tanh(a.y + b.y);
        float2 c = __half22float2(ph1[j]);
        float2 d = __half22float2(qh1[j]);
        th[8 + 2 * j]     = fast_tanh(c.x + d.x);
        th[8 + 2 * j + 1] = fast_tanh(c.y + d.y);
    }

    float part = 0.f;
    if (spatial) {
        const float* w = &Wpos[4 + sub * 16];
#pragma unroll
        for (int j = 0; j < 16; j++) part += th[j] * w[j];
        if (sub == 0) {
            float4 a = *reinterpret_cast<const float4*>(&sattr[(size_t)e * 4]);
            part += a.x * Wpos[0] + a.y * Wpos[1] + a.z * Wpos[2] + a.w * Wpos[3];
        }
    } else {
        const float* w = &Wdom[1 + sub * 16];
#pragma unroll
        for (int j = 0; j < 16; j++) part += th[j] * w[j];
        if (sub == 0) part += dattr[e] * Wdom[0];
    }

    part += __shfl_xor_sync(0xFFFFFFFFu, part, 1);

    float logit = part + (spatial ? bpos[0] : bdom[0]);
    float ew = 1.f / (1.f + __expf(-logit));
    if (sub == 0) { if (spatial) g_ew_s[e] = ew; else g_ew_d[e] = ew; }

    // ---- fused round-1 propagation: data already in registers ----
    {
        unsigned int* dn = reinterpret_cast<unsigned int*>(nrow);
        const __half2* sh = reinterpret_cast<const __half2*>(&sr);
        float2 s0 = __half22float2(sh[0]);
        float2 s1 = __half22float2(sh[1]);
        float2 s2 = __half22float2(sh[2]);
        float2 s3 = __half22float2(sh[3]);
        float v0 = s0.x * ew, v1 = s0.y * ew, v2 = s1.x * ew, v3 = s1.y * ew;
        float v4 = s2.x * ew, v5 = s2.y * ew, v6 = s3.x * ew, v7 = s3.y * ew;
        if (v0 > dA.x) atomicMax(dn + 0, __float_as_uint(v0));
        if (v1 > dA.y) atomicMax(dn + 1, __float_as_uint(v1));
        if (v2 > dA.z) atomicMax(dn + 2, __float_as_uint(v2));
        if (v3 > dA.w) atomicMax(dn + 3, __float_as_uint(v3));
        if (v4 > dB.x) atomicMax(dn + 4, __float_as_uint(v4));
        if (v5 > dB.y) atomicMax(dn + 5, __float_as_uint(v5));
        if (v6 > dB.z) atomicMax(dn + 6, __float_as_uint(v6));
        if (v7 > dB.w) atomicMax(dn + 7, __float_as_uint(v7));
    }
}

// ---------------- kernel 3: convert n32 -> c16 (2 rows/thread) ------------
__global__ void convert_kernel() {
    int i = blockIdx.x * blockDim.x + threadIdx.x;   // 8-float chunk index
    const int n8 = NN * MDIM / 8;
    if (i >= n8) return;
    const float4* pp = reinterpret_cast<const float4*>(g_n32pos) + i * 2;
    const float4* dp = reinterpret_cast<const float4*>(g_n32dom) + i * 2;
    float4 pA = pp[0], pB = pp[1];
    float4 dA = dp[0], dB = dp[1];
    __half2 h;
    uint4 po, dd;
    h = __floats2half2_rn(pA.x, pA.y); po.x = *reinterpret_cast<unsigned*>(&h);
    h = __floats2half2_rn(pA.z, pA.w); po.y = *reinterpret_cast<unsigned*>(&h);
    h = __floats2half2_rn(pB.x, pB.y); po.z = *reinterpret_cast<unsigned*>(&h);
    h = __floats2half2_rn(pB.z, pB.w); po.w = *reinterpret_cast<unsigned*>(&h);
    h = __floats2half2_rn(dA.x, dA.y); dd.x = *reinterpret_cast<unsigned*>(&h);
    h = __floats2half2_rn(dA.z, dA.w); dd.y = *reinterpret_cast<unsigned*>(&h);
    h = __floats2half2_rn(dB.x, dB.y); dd.z = *reinterpret_cast<unsigned*>(&h);
    h = __floats2half2_rn(dB.z, dB.w); dd.w = *reinterpret_cast<unsigned*>(&h);
    reinterpret_cast<uint4*>(g_c16pos)[i] = po;
    reinterpret_cast<uint4*>(g_c16dom)[i] = dd;
}

// ---------------- kernel 4: propagation rounds 2-3 (mirror filter) ---------
__global__ void prop_kernel(const int* __restrict__ si, const int* __restrict__ di) {
    long long t = (long long)blockIdx.x * blockDim.x + threadIdx.x;
    if (t >= (long long)ES * 2) return;
    int p = (int)(t >> 1);       // edge id in each set
    int sub = (int)(t & 1);      // half-row (8 channels)

    int s0 = si[p], d0 = si[ES + p];
    int s1 = di[p], d1 = di[ED + p];
    float ew0 = g_ew_s[p];
    float ew1 = g_ew_d[p];

    uint4 sr0 = *reinterpret_cast<const uint4*>(&g_c16pos[(size_t)s0 * MDIM + sub * 8]);
    uint4 dr0 = *reinterpret_cast<const uint4*>(&g_c16pos[(size_t)d0 * MDIM + sub * 8]);
    uint4 sr1 = *reinterpret_cast<const uint4*>(&g_c16dom[(size_t)s1 * MDIM + sub * 8]);
    uint4 dr1 = *reinterpret_cast<const uint4*>(&g_c16dom[(size_t)d1 * MDIM + sub * 8]);

    {
        const __half2* sh = reinterpret_cast<const __half2*>(&sr0);
        const __half2* dh = reinterpret_cast<const __half2*>(&dr0);
        unsigned int* dn = reinterpret_cast<unsigned int*>(&g_n32pos[(size_t)d0 * MDIM + sub * 8]);
#pragma unroll
        for (int j = 0; j < 4; j++) {
            float2 s = __half22float2(sh[j]);
            float2 d = __half22float2(dh[j]);
            float v0 = s.x * ew0, v1 = s.y * ew0;
            if (v0 > d.x) atomicMax(dn + 2 * j + 0, __float_as_uint(v0));
            if (v1 > d.y) atomicMax(dn + 2 * j + 1, __float_as_uint(v1));
        }
    }
    {
        const __half2* sh = reinterpret_cast<const __half2*>(&sr1);
        const __half2* dh = reinterpret_cast<const __half2*>(&dr1);
        unsigned int* dn = reinterpret_cast<unsigned int*>(&g_n32dom[(size_t)d1 * MDIM + sub * 8]);
#pragma unroll
        for (int j = 0; j < 4; j++) {
            float2 s = __half22float2(sh[j]);
            float2 d = __half22float2(dh[j]);
            float v0 = s.x * ew1, v1 = s.y * ew1;
            if (v0 > d.x) atomicMax(dn + 2 * j + 0, __float_as_uint(v0));
            if (v1 > d.y) atomicMax(dn + 2 * j + 1, __float_as_uint(v1));
        }
    }
}

// ---------------- kernel 5: final max --------------------------------------
__global__ void final_kernel(const float* __restrict__ mask, float* __restrict__ out) {
    int i = blockIdx.x * blockDim.x + threadIdx.x;
    const int n4 = NN * MDIM / 4;
    if (i >= n4) return;
    float4 m = reinterpret_cast<const float4*>(mask)[i];
    float4 p = reinterpret_cast<const float4*>(g_n32pos)[i];
    float4 d = reinterpret_cast<const float4*>(g_n32dom)[i];
    float4 r;
    r.x = fmaxf(m.x, fmaxf(p.x, d.x));
    r.y = fmaxf(m.y, fmaxf(p.y, d.y));
    r.z = fmaxf(m.z, fmaxf(p.z, d.z));
    r.w = fmaxf(m.w, fmaxf(p.w, d.w));
    reinterpret_cast<float4*>(out)[i] = r;
}

// ---------------- launch -------------------------------------------------
extern "C" void kernel_launch(void* const* d_in, const int* in_sizes, int n_in,
                              void* d_out, int out_size) {
    const float* x     = (const float*)d_in[0];
    const float* mask  = (const float*)d_in[1];
    const int*   si    = (const int*)d_in[2];
    const int*   di    = (const int*)d_in[3];
    const float* sattr = (const float*)d_in[4];
    const float* dattr = (const float*)d_in[5];
    const float* Wt    = (const float*)d_in[6];
    const float* bt    = (const float*)d_in[7];
    const float* Wpos  = (const float*)d_in[8];
    const float* bpos  = (const float*)d_in[9];
    const float* Wdom  = (const float*)d_in[10];
    const float* bdom  = (const float*)d_in[11];
    float* out = (float*)d_out;

    const int n4 = NN * MDIM / 4;
    const int n8 = NN * MDIM / 8;
    const int cgrid = (n4 + 255) / 256;

    // 1. HMMA node projections + fused mask-buffer init
    proj_kernel<<<(NN + 63) / 64, 128>>>(x, Wt, bt, mask);

    // 2. fused gate + propagation round 1 (2 lanes/edge, hoisted loads)
    {
        long long threads = (long long)(ES + ED) * 2;
        int blk = 256;
        long long grid = (threads + blk - 1) / blk;
        ewprop_kernel<<<(unsigned)grid, blk>>>(si, di, sattr, dattr, Wpos, bpos, Wdom, bdom);
    }

    // 3. rounds 2-3: convert / prop / convert / prop
    {
        long long threads = (long long)ES * 2;   // 2 edges (one per set) per thread
        int blk = 256;
        long long grid = (threads + blk - 1) / blk;

        convert_kernel<<<(n8 + 255) / 256, 256>>>();
        prop_kernel<<<(unsigned)grid, blk>>>(si, di);
        convert_kernel<<<(n8 + 255) / 256, 256>>>();
        prop_kernel<<<(unsigned)grid, blk>>>(si, di);
    }

    // 4. final: max(mask, pos, dom)
    final_kernel<<<cgrid, 256>>>(mask, out);
}

// round 17
// speedup vs baseline: 1.0385x; 1.0385x over previous
#include <cuda_runtime.h>
#include <cuda_fp16.h>
#include <cstdint>

#define NN     100000
#define HH     128
#define TT     32
#define MDIM   16
#define ES     600000
#define ED     600000

// ---------------- scratch ----------------
__device__ __align__(16) __half g_Ps[NN * TT];   // fp16 x@W[:H]
__device__ __align__(16) __half g_Pd[NN * TT];   // fp16 x@W[H:] + b_trans
__device__ float g_ew_s[ES];
__device__ float g_ew_d[ED];
// propagation state: fp32 accumulator (atomics) + fp16 read mirror
__device__ __align__(16) float  g_n32pos[NN * MDIM];
__device__ __align__(16) float  g_n32dom[NN * MDIM];
__device__ __align__(16) __half g_c16pos[NN * MDIM];
__device__ __align__(16) __half g_c16dom[NN * MDIM];

// ---------------- helpers ----------------
__device__ __forceinline__ float fast_tanh(float s) {
    float r; asm("tanh.approx.f32 %0, %1;" : "=f"(r) : "f"(s)); return r;
}
__device__ __forceinline__ unsigned su32(const void* p) {
    return (unsigned)__cvta_generic_to_shared(p);
}

// ---------------- kernel 1: HMMA node projections + fused init -------------
#define XS_STRIDE 136
#define WP_STRIDE 72

__global__ void __launch_bounds__(128) proj_kernel(const float* __restrict__ x,
                                                   const float* __restrict__ Wt,
                                                   const float* __restrict__ bt,
                                                   const float* __restrict__ mask) {
    __shared__ __align__(16) __half Wp[128 * WP_STRIDE];
    __shared__ __align__(16) __half xs[64 * XS_STRIDE];
    int tid = threadIdx.x;
    int n0 = blockIdx.x * 64;

    // ---- fused init: mask -> n32 (fp32) + c16 (fp16), grid-stride ----
    {
        const int n4 = NN * MDIM / 4;
        for (int i = blockIdx.x * 128 + tid; i < n4; i += gridDim.x * 128) {
            float4 v = reinterpret_cast<const float4*>(mask)[i];
            reinterpret_cast<float4*>(g_n32pos)[i] = v;
            reinterpret_cast<float4*>(g_n32dom)[i] = v;
            __half2 h0 = __floats2half2_rn(v.x, v.y);
            __half2 h1 = __floats2half2_rn(v.z, v.w);
            uint2 packed = make_uint2(*reinterpret_cast<unsigned*>(&h0),
                                      *reinterpret_cast<unsigned*>(&h1));
            reinterpret_cast<uint2*>(g_c16pos)[i] = packed;
            reinterpret_cast<uint2*>(g_c16dom)[i] = packed;
        }
    }

    for (int i = tid; i < 128 * 64; i += 128) {
        int h = i >> 6, j = i & 63;
        float w = (j < 32) ? Wt[h * 32 + j] : Wt[(128 + h) * 32 + (j - 32)];
        Wp[h * WP_STRIDE + j] = __float2half_rn(w);
    }
    for (int i = tid; i < 64 * 32; i += 128) {
        int r = i >> 5, c4 = i & 31;
        int node = n0 + r;
        float4 v = (node < NN)
                 ? reinterpret_cast<const float4*>(x)[(size_t)node * 32 + c4]
                 : make_float4(0.f, 0.f, 0.f, 0.f);
        *reinterpret_cast<__half2*>(&xs[r * XS_STRIDE + c4 * 4])     = __floats2half2_rn(v.x, v.y);
        *reinterpret_cast<__half2*>(&xs[r * XS_STRIDE + c4 * 4 + 2]) = __floats2half2_rn(v.z, v.w);
    }
    __syncthreads();

    int warp = tid >> 5, lane = tid & 31;
    int wb = warp * 16;

    float acc[8][4];
#pragma unroll
    for (int nt = 0; nt < 8; nt++)
#pragma unroll
        for (int j = 0; j < 4; j++) acc[nt][j] = 0.f;

    int a_row = wb + (lane & 15);
    int a_coff = (lane >> 4) * 8;
    int b_row = (lane & 15);

#pragma unroll
    for (int k = 0; k < 8; k++) {
        unsigned a0, a1, a2, a3;
        unsigned addrA = su32(&xs[a_row * XS_STRIDE + k * 16 + a_coff]);
        asm volatile("ldmatrix.sync.aligned.m8n8.x4.shared.b16 {%0,%1,%2,%3}, [%4];"
                     : "=r"(a0), "=r"(a1), "=r"(a2), "=r"(a3) : "r"(addrA));
#pragma unroll
        for (int nt = 0; nt < 8; nt++) {
            unsigned b0, b1;
            unsigned addrB = su32(&Wp[(k * 16 + b_row) * WP_STRIDE + nt * 8]);
            asm volatile("ldmatrix.sync.aligned.m8n8.x2.trans.shared.b16 {%0,%1}, [%2];"
                         : "=r"(b0), "=r"(b1) : "r"(addrB));
            asm volatile("mma.sync.aligned.m16n8k16.row.col.f32.f16.f16.f32 "
                         "{%0,%1,%2,%3}, {%4,%5,%6,%7}, {%8,%9}, {%0,%1,%2,%3};"
                         : "+f"(acc[nt][0]), "+f"(acc[nt][1]), "+f"(acc[nt][2]), "+f"(acc[nt][3])
                         : "r"(a0), "r"(a1), "r"(a2), "r"(a3), "r"(b0), "r"(b1));
        }
    }

    int row_l = wb + (lane >> 2);
    int col0 = (lane & 3) * 2;
#pragma unroll
    for (int nt = 0; nt < 8; nt++) {
        bool isPs = (nt < 4);
        __half* base = isPs ? g_Ps : g_Pd;
        int cc = isPs ? (nt * 8 + col0) : (nt * 8 + col0 - 32);
        float b0 = isPs ? 0.f : bt[cc];
        float b1 = isPs ? 0.f : bt[cc + 1];
        int nodeA = n0 + row_l;
        int nodeB = nodeA + 8;
        if (nodeA < NN)
            *reinterpret_cast<__half2*>(&base[(size_t)nodeA * TT + cc]) =
                __floats2half2_rn(acc[nt][0] + b0, acc[nt][1] + b1);
        if (nodeB < NN)
            *reinterpret_cast<__half2*>(&base[(size_t)nodeB * TT + cc]) =
                __floats2half2_rn(acc[nt][2] + b0, acc[nt][3] + b1);
    }
}

// ---------------- kernel 2: FUSED gate + propagation round 1 ---------------
// 2 lanes/edge; gate loads first, compute, then FRESH phase-2 loads for the
// live filter (R15 structure: best measured).
__global__ void ewprop_kernel(const int* __restrict__ si, const int* __restrict__ di,
                              const float* __restrict__ sattr, const float* __restrict__ dattr,
                              const float* __restrict__ Wpos, const float* __restrict__ bpos,
                              const float* __restrict__ Wdom, const float* __restrict__ bdom) {
    long long gid = (long long)blockIdx.x * blockDim.x + threadIdx.x;
    long long eg = gid >> 1;
    int sub = (int)(gid & 1);      // half: channels [sub*16, sub*16+16)
    if (eg >= (long long)(ES + ED)) return;

    bool spatial = (eg < ES);
    int e = spatial ? (int)eg : (int)(eg - ES);
    const int* eidx = spatial ? si : di;
    int nE = spatial ? ES : ED;
    int src = eidx[e];
    int dst = eidx[nE + e];

    const __half* psrow = &g_Ps[(size_t)src * TT + sub * 16];
    const __half* pdrow = &g_Pd[(size_t)dst * TT + sub * 16];
    uint4 pa0 = *reinterpret_cast<const uint4*>(psrow);
    uint4 pa1 = *reinterpret_cast<const uint4*>(psrow + 8);
    uint4 pb0 = *reinterpret_cast<const uint4*>(pdrow);
    uint4 pb1 = *reinterpret_cast<const uint4*>(pdrow + 8);
    const __half2* ph0 = reinterpret_cast<const __half2*>(&pa0);
    const __half2* ph1 = reinterpret_cast<const __half2*>(&pa1);
    const __half2* qh0 = reinterpret_cast<const __half2*>(&pb0);
    const __half2* qh1 = reinterpret_cast<const __half2*>(&pb1);

    float th[16];
#pragma unroll
    for (int j = 0; j < 4; j++) {
        float2 a = __half22float2(ph0[j]);
        float2 b = __half22float2(qh0[j]);
        th[2 * j]     = fast_tanh(a.x + b.x);
        th[2 * j + 1] = fast_tanh(a.y + b.y);
        float2 c = __half22float2(ph1[j]);
        float2 d = __half22float2(qh1[j]);
        th[8 + 2 * j]     = fast_tanh(c.x + d.x);
        th[8 + 2 * j + 1] = fast_tanh(c.y + d.y);
    }

    float part = 0.f;
    if (spatial) {
        const float* w = &Wpos[4 + sub * 16];
#pragma unroll
        for (int j = 0; j < 16; j++) part += th[j] * w[j];
        if (sub == 0) {
            float4 a = *reinterpret_cast<const float4*>(&sattr[(size_t)e * 4]);
            part += a.x * Wpos[0] + a.y * Wpos[1] + a.z * Wpos[2] + a.w * Wpos[3];
        }
    } else {
        const float* w = &Wdom[1 + sub * 16];
#pragma unroll
        for (int j = 0; j < 16; j++) part += th[j] * w[j];
        if (sub == 0) part += dattr[e] * Wdom[0];
    }

    part += __shfl_xor_sync(0xFFFFFFFFu, part, 1);

    float logit = part + (spatial ? bpos[0] : bdom[0]);
    float ew = 1.f / (1.f + __expf(-logit));
    if (sub == 0) { if (spatial) g_ew_s[e] = ew; else g_ew_d[e] = ew; }

    // ---- fused round-1 propagation: fresh loads + live filter ----
    {
        const __half* c = spatial ? g_c16pos : g_c16dom;
        float* n = spatial ? g_n32pos : g_n32dom;
        uint4 sr = *reinterpret_cast<const uint4*>(&c[(size_t)src * MDIM + sub * 8]);
        const float4* drow = reinterpret_cast<const float4*>(&n[(size_t)dst * MDIM + sub * 8]);
        float4 dA = drow[0], dB = drow[1];
        const __half2* sh = reinterpret_cast<const __half2*>(&sr);
        unsigned int* dn = reinterpret_cast<unsigned int*>(&n[(size_t)dst * MDIM + sub * 8]);

        float2 s0 = __half22float2(sh[0]);
        float2 s1 = __half22float2(sh[1]);
        float2 s2 = __half22float2(sh[2]);
        float2 s3 = __half22float2(sh[3]);
        float v0 = s0.x * ew, v1 = s0.y * ew, v2 = s1.x * ew, v3 = s1.y * ew;
        float v4 = s2.x * ew, v5 = s2.y * ew, v6 = s3.x * ew, v7 = s3.y * ew;
        if (v0 > dA.x) atomicMax(dn + 0, __float_as_uint(v0));
        if (v1 > dA.y) atomicMax(dn + 1, __float_as_uint(v1));
        if (v2 > dA.z) atomicMax(dn + 2, __float_as_uint(v2));
        if (v3 > dA.w) atomicMax(dn + 3, __float_as_uint(v3));
        if (v4 > dB.x) atomicMax(dn + 4, __float_as_uint(v4));
        if (v5 > dB.y) atomicMax(dn + 5, __float_as_uint(v5));
        if (v6 > dB.z) atomicMax(dn + 6, __float_as_uint(v6));
        if (v7 > dB.w) atomicMax(dn + 7, __float_as_uint(v7));
    }
}

// ---------------- kernel 3: convert n32 -> c16 (4 chunks/thread) ----------
__global__ void convert_kernel() {
    int i = blockIdx.x * blockDim.x + threadIdx.x;   // 16-float chunk index
    const int n16 = NN * MDIM / 16;
    if (i >= n16) return;
    const float4* pp = reinterpret_cast<const float4*>(g_n32pos) + i * 4;
    const float4* dp = reinterpret_cast<const float4*>(g_n32dom) + i * 4;
    float4 p0 = pp[0], p1 = pp[1], p2 = pp[2], p3 = pp[3];
    float4 d0 = dp[0], d1 = dp[1], d2 = dp[2], d3 = dp[3];
    __half2 h;
    uint4 poA, poB, ddA, ddB;
    h = __floats2half2_rn(p0.x, p0.y); poA.x = *reinterpret_cast<unsigned*>(&h);
    h = __floats2half2_rn(p0.z, p0.w); poA.y = *reinterpret_cast<unsigned*>(&h);
    h = __floats2half2_rn(p1.x, p1.y); poA.z = *reinterpret_cast<unsigned*>(&h);
    h = __floats2half2_rn(p1.z, p1.w); poA.w = *reinterpret_cast<unsigned*>(&h);
    h = __floats2half2_rn(p2.x, p2.y); poB.x = *reinterpret_cast<unsigned*>(&h);
    h = __floats2half2_rn(p2.z, p2.w); poB.y = *reinterpret_cast<unsigned*>(&h);
    h = __floats2half2_rn(p3.x, p3.y); poB.z = *reinterpret_cast<unsigned*>(&h);
    h = __floats2half2_rn(p3.z, p3.w); poB.w = *reinterpret_cast<unsigned*>(&h);
    h = __floats2half2_rn(d0.x, d0.y); ddA.x = *reinterpret_cast<unsigned*>(&h);
    h = __floats2half2_rn(d0.z, d0.w); ddA.y = *reinterpret_cast<unsigned*>(&h);
    h = __floats2half2_rn(d1.x, d1.y); ddA.z = *reinterpret_cast<unsigned*>(&h);
    h = __floats2half2_rn(d1.z, d1.w); ddA.w = *reinterpret_cast<unsigned*>(&h);
    h = __floats2half2_rn(d2.x, d2.y); ddB.x = *reinterpret_cast<unsigned*>(&h);
    h = __floats2half2_rn(d2.z, d2.w); ddB.y = *reinterpret_cast<unsigned*>(&h);
    h = __floats2half2_rn(d3.x, d3.y); ddB.z = *reinterpret_cast<unsigned*>(&h);
    h = __floats2half2_rn(d3.z, d3.w); ddB.w = *reinterpret_cast<unsigned*>(&h);
    reinterpret_cast<uint4*>(g_c16pos)[i * 2]     = poA;
    reinterpret_cast<uint4*>(g_c16pos)[i * 2 + 1] = poB;
    reinterpret_cast<uint4*>(g_c16dom)[i * 2]     = ddA;
    reinterpret_cast<uint4*>(g_c16dom)[i * 2 + 1] = ddB;
}

// ---------------- kernel 4: propagation rounds 2-3 (mirror filter) ---------
__global__ void prop_kernel(const int* __restrict__ si, const int* __restrict__ di) {
    long long t = (long long)blockIdx.x * blockDim.x + threadIdx.x;
    if (t >= (long long)ES * 2) return;
    int p = (int)(t >> 1);       // edge id in each set
    int sub = (int)(t & 1);      // half-row (8 channels)

    int s0 = si[p], d0 = si[ES + p];
    int s1 = di[p], d1 = di[ED + p];
    float ew0 = g_ew_s[p];
    float ew1 = g_ew_d[p];

    uint4 sr0 = *reinterpret_cast<const uint4*>(&g_c16pos[(size_t)s0 * MDIM + sub * 8]);
    uint4 dr0 = *reinterpret_cast<const uint4*>(&g_c16pos[(size_t)d0 * MDIM + sub * 8]);
    uint4 sr1 = *reinterpret_cast<const uint4*>(&g_c16dom[(size_t)s1 * MDIM + sub * 8]);
    uint4 dr1 = *reinterpret_cast<const uint4*>(&g_c16dom[(size_t)d1 * MDIM + sub * 8]);

    {
        const __half2* sh = reinterpret_cast<const __half2*>(&sr0);
        const __half2* dh = reinterpret_cast<const __half2*>(&dr0);
        unsigned int* dn = reinterpret_cast<unsigned int*>(&g_n32pos[(size_t)d0 * MDIM + sub * 8]);
#pragma unroll
        for (int j = 0; j < 4; j++) {
            float2 s = __half22float2(sh[j]);
            float2 d = __half22float2(dh[j]);
            float v0 = s.x * ew0, v1 = s.y * ew0;
            if (v0 > d.x) atomicMax(dn + 2 * j + 0, __float_as_uint(v0));
            if (v1 > d.y) atomicMax(dn + 2 * j + 1, __float_as_uint(v1));
        }
    }
    {
        const __half2* sh = reinterpret_cast<const __half2*>(&sr1);
        const __half2* dh = reinterpret_cast<const __half2*>(&dr1);
        unsigned int* dn = reinterpret_cast<unsigned int*>(&g_n32dom[(size_t)d1 * MDIM + sub * 8]);
#pragma unroll
        for (int j = 0; j < 4; j++) {
            float2 s = __half22float2(sh[j]);
            float2 d = __half22float2(dh[j]);
            float v0 = s.x * ew1, v1 = s.y * ew1;
            if (v0 > d.x) atomicMax(dn + 2 * j + 0, __float_as_uint(v0));
            if (v1 > d.y) atomicMax(dn + 2 * j + 1, __float_as_uint(v1));
        }
    }
}

// ---------------- kernel 5: final max (2 float4 per thread) ----------------
__global__ void final_kernel(const float* __restrict__ mask, float* __restrict__ out) {
    int i = blockIdx.x * blockDim.x + threadIdx.x;
    const int n8 = NN * MDIM / 8;
    if (i >= n8) return;
    const float4* mp = reinterpret_cast<const float4*>(mask) + i * 2;
    const float4* pp = reinterpret_cast<const float4*>(g_n32pos) + i * 2;
    const float4* dp = reinterpret_cast<const float4*>(g_n32dom) + i * 2;
    float4 m0 = mp[0], m1 = mp[1];
    float4 p0 = pp[0], p1 = pp[1];
    float4 d0 = dp[0], d1 = dp[1];
    float4 r0, r1;
    r0.x = fmaxf(m0.x, fmaxf(p0.x, d0.x));
    r0.y = fmaxf(m0.y, fmaxf(p0.y, d0.y));
    r0.z = fmaxf(m0.z, fmaxf(p0.z, d0.z));
    r0.w = fmaxf(m0.w, fmaxf(p0.w, d0.w));
    r1.x = fmaxf(m1.x, fmaxf(p1.x, d1.x));
    r1.y = fmaxf(m1.y, fmaxf(p1.y, d1.y));
    r1.z = fmaxf(m1.z, fmaxf(p1.z, d1.z));
    r1.w = fmaxf(m1.w, fmaxf(p1.w, d1.w));
    reinterpret_cast<float4*>(out)[i * 2]     = r0;
    reinterpret_cast<float4*>(out)[i * 2 + 1] = r1;
}

// ---------------- launch -------------------------------------------------
extern "C" void kernel_launch(void* const* d_in, const int* in_sizes, int n_in,
                              void* d_out, int out_size) {
    const float* x     = (const float*)d_in[0];
    const float* mask  = (const float*)d_in[1];
    const int*   si    = (const int*)d_in[2];
    const int*   di    = (const int*)d_in[3];
    const float* sattr = (const float*)d_in[4];
    const float* dattr = (const float*)d_in[5];
    const float* Wt    = (const float*)d_in[6];
    const float* bt    = (const float*)d_in[7];
    const float* Wpos  = (const float*)d_in[8];
    const float* bpos  = (const float*)d_in[9];
    const float* Wdom  = (const float*)d_in[10];
    const float* bdom  = (const float*)d_in[11];
    float* out = (float*)d_out;

    const int n8 = NN * MDIM / 8;
    const int n16 = NN * MDIM / 16;

    // 1. HMMA node projections + fused mask-buffer init
    proj_kernel<<<(NN + 63) / 64, 128>>>(x, Wt, bt, mask);

    // 2. fused gate + propagation round 1 (2 lanes/edge, live filter)
    {
        long long threads = (long long)(ES + ED) * 2;
        int blk = 256;
        long long grid = (threads + blk - 1) / blk;
        ewprop_kernel<<<(unsigned)grid, blk>>>(si, di, sattr, dattr, Wpos, bpos, Wdom, bdom);
    }

    // 3. rounds 2-3: convert / prop / convert / prop
    {
        long long threads = (long long)ES * 2;   // 2 edges (one per set) per thread
        int blk = 256;
        long long grid = (threads + blk - 1) / blk;

        convert_kernel<<<(n16 + 255) / 256, 256>>>();
        prop_kernel<<<(unsigned)grid, blk>>>(si, di);
        convert_kernel<<<(n16 + 255) / 256, 256>>>();
        prop_kernel<<<(unsigned)grid, blk>>>(si, di);
    }

    // 4. final: max(mask, pos, dom)
    final_kernel<<<(n8 + 255) / 256, 256>>>(mask, out);
}